// round 3
// baseline (speedup 1.0000x reference)
#include <cuda_runtime.h>
#include <math.h>
#include <float.h>

// layers: C = {64,128,256,512}, HW = {3136,784,196,49}, B=256, R=2000
#define NB 256
#define NR 2000
#define NRP 2048

__constant__ int c_C[4]    = {64, 128, 256, 512};
__constant__ int c_HW[4]   = {3136, 784, 196, 49};
__constant__ int c_qoff[4] = {0, 16384, 49152, 114688};

// scratch (static device globals; no allocation)
__device__ __align__(16) float g_fq[245760];         // pooled queries
__device__ __align__(16) float g_dist[4 * NB * NRP]; // squared distances, padded w/ FLT_MAX
__device__ float g_r2[4 * NR];
__device__ float g_q2[4 * NB];
__device__ float g_lid[NB * 4];

// ---------------- kernel 1: spatial mean pooling (warp per (b,c) row) ----------------
__global__ void __launch_bounds__(256) pool_kernel(
    const float* __restrict__ f0, const float* __restrict__ f1,
    const float* __restrict__ f2, const float* __restrict__ f3)
{
    int gw   = (blockIdx.x * 256 + threadIdx.x) >> 5;
    int lane = threadIdx.x & 31;
    if (gw >= 245760) return;

    int l, base;
    if      (gw < 16384)  { l = 0; base = 0; }
    else if (gw < 49152)  { l = 1; base = 16384; }
    else if (gw < 114688) { l = 2; base = 49152; }
    else                  { l = 3; base = 114688; }
    int row = gw - base;
    const float* f = (l == 0) ? f0 : (l == 1) ? f1 : (l == 2) ? f2 : f3;
    int HW = c_HW[l];
    const float* src = f + (size_t)row * HW;

    float s = 0.f;
    if (l < 3) {
        const float4* s4 = (const float4*)src;
        int n4 = HW >> 2;
        for (int i = lane; i < n4; i += 32) {
            float4 v = s4[i];
            s += (v.x + v.y) + (v.z + v.w);
        }
    } else {
        for (int i = lane; i < HW; i += 32) s += src[i];
    }
    #pragma unroll
    for (int o = 16; o > 0; o >>= 1) s += __shfl_xor_sync(0xffffffffu, s, o);
    if (lane == 0) g_fq[c_qoff[l] + row] = s / (float)HW;
}

// ---------------- kernel 2: squared norms of refs and pooled queries ----------------
__global__ void __launch_bounds__(256) norms_kernel(
    const float* __restrict__ r0, const float* __restrict__ r1,
    const float* __restrict__ r2, const float* __restrict__ r3)
{
    int gw   = (blockIdx.x * 256 + threadIdx.x) >> 5;
    int lane = threadIdx.x & 31;
    if (gw >= 9024) return;

    const float* src;
    float* out;
    int C;
    if (gw < 8000) {
        int l = gw / NR, row = gw % NR;
        const float* rp = (l == 0) ? r0 : (l == 1) ? r1 : (l == 2) ? r2 : r3;
        C = c_C[l];
        src = rp + (size_t)row * C;
        out = g_r2 + l * NR + row;
    } else {
        int idx = gw - 8000;
        int l = idx >> 8, row = idx & 255;
        C = c_C[l];
        src = g_fq + c_qoff[l] + (size_t)row * C;
        out = g_q2 + l * NB + row;
    }
    float s = 0.f;
    const float4* s4 = (const float4*)src;
    int n4 = C >> 2;
    for (int i = lane; i < n4; i += 32) {
        float4 v = s4[i];
        s += v.x * v.x + v.y * v.y + v.z * v.z + v.w * v.w;
    }
    #pragma unroll
    for (int o = 16; o > 0; o >>= 1) s += __shfl_xor_sync(0xffffffffu, s, o);
    if (lane == 0) *out = s;
}

// ---------------- kernel 3: distances, 64x64 tile, 16 acc/thread ----------------
__global__ void __launch_bounds__(256) dist_gemm_kernel(
    const float* __restrict__ r0, const float* __restrict__ r1,
    const float* __restrict__ r2, const float* __restrict__ r3)
{
    int l = blockIdx.z;
    int C = c_C[l];
    const float* ref = (l == 0) ? r0 : (l == 1) ? r1 : (l == 2) ? r2 : r3;
    const float* q   = g_fq + c_qoff[l];

    int bt = blockIdx.y << 6;   // batch tile base (64)
    int rt = blockIdx.x << 6;   // ref tile base (64)

    __shared__ __align__(16) float qs[16][68];  // [k][b], 272B rows: float4-aligned, conflict-skewed
    __shared__ __align__(16) float rs[16][68];  // [k][r]

    int tx = threadIdx.x, ty = threadIdx.y;
    int tid = ty * 16 + tx;

    float acc[4][4];
    #pragma unroll
    for (int i = 0; i < 4; i++)
        #pragma unroll
        for (int j = 0; j < 4; j++) acc[i][j] = 0.f;

    for (int c0 = 0; c0 < C; c0 += 16) {
        #pragma unroll
        for (int i = 0; i < 4; i++) {
            int idx = tid + i * 256;
            int row = idx >> 4, kk = idx & 15;
            qs[kk][row] = q[(size_t)(bt + row) * C + c0 + kk];
            int rr = rt + row;
            rs[kk][row] = (rr < NR) ? ref[(size_t)rr * C + c0 + kk] : 0.f;
        }
        __syncthreads();
        #pragma unroll
        for (int kk = 0; kk < 16; kk++) {
            float4 qv = *(const float4*)&qs[kk][ty * 4];
            float4 rv = *(const float4*)&rs[kk][tx * 4];
            float qa[4] = {qv.x, qv.y, qv.z, qv.w};
            float ra[4] = {rv.x, rv.y, rv.z, rv.w};
            #pragma unroll
            for (int i = 0; i < 4; i++)
                #pragma unroll
                for (int j = 0; j < 4; j++)
                    acc[i][j] += qa[i] * ra[j];
        }
        __syncthreads();
    }

    // epilogue: d = q2 + r2 - 2*dot, pad with FLT_MAX
    float q2v[4], r2v[4];
    #pragma unroll
    for (int i = 0; i < 4; i++) q2v[i] = g_q2[l * NB + bt + ty * 4 + i];
    #pragma unroll
    for (int j = 0; j < 4; j++) {
        int rr = rt + tx * 4 + j;
        r2v[j] = (rr < NR) ? g_r2[l * NR + rr] : 0.f;
    }

    float* out = g_dist + ((size_t)l * NB + bt) * NRP + rt;
    #pragma unroll
    for (int i = 0; i < 4; i++) {
        int b = ty * 4 + i;
        float4 o;
        float* oc = &o.x;
        #pragma unroll
        for (int j = 0; j < 4; j++) {
            int rr = rt + tx * 4 + j;
            oc[j] = (rr < NR) ? (q2v[i] + r2v[j] - 2.f * acc[i][j]) : FLT_MAX;
        }
        *(float4*)&out[(size_t)b * NRP + tx * 4] = o;
    }
}

// ---------------- kernel 4: warp-local top-(k+1) + merge + LID ----------------
__global__ void __launch_bounds__(256) select_kernel(const int* __restrict__ kp)
{
    int b = blockIdx.x;
    int l = blockIdx.y;
    int tid  = threadIdx.x;
    int warp = tid >> 5;
    int lane = tid & 31;

    __shared__ float cand[8 * 64];   // 8 warps x up to 64 sorted candidates
    __shared__ float topd[64];

    const float* dp = g_dist + ((size_t)l * NB + b) * NRP;

    // each lane owns 8 contiguous distances; warp owns 256 contiguous
    int base = warp * 256 + lane * 8;
    float4 a4 = *(const float4*)&dp[base];
    float4 c4 = *(const float4*)&dp[base + 4];
    float v[8] = {a4.x, a4.y, a4.z, a4.w, c4.x, c4.y, c4.z, c4.w};

    int kk  = *kp;
    int kp1 = min(kk + 1, 64);

    // phase A: per-warp extraction of local top-kp1 (sorted ascending), no block barriers
    for (int t = 0; t < kp1; t++) {
        float m = v[0]; int mj = 0;
        #pragma unroll
        for (int j = 1; j < 8; j++) if (v[j] < m) { m = v[j]; mj = j; }
        int idx = lane * 8 + mj;     // within-warp element index
        #pragma unroll
        for (int o = 16; o > 0; o >>= 1) {
            float om = __shfl_xor_sync(0xffffffffu, m, o);
            int   oi = __shfl_xor_sync(0xffffffffu, idx, o);
            if (om < m || (om == m && oi < idx)) { m = om; idx = oi; }
        }
        if (lane == (idx >> 3)) {
            int j = idx & 7;
            #pragma unroll
            for (int jj = 0; jj < 8; jj++) if (j == jj) v[jj] = FLT_MAX;
        }
        if (lane == 0) cand[warp * 64 + t] = m;
    }
    __syncthreads();

    // phase B: warp 0 merges 8 sorted lists via head pointers (lanes 0..7 are heads)
    if (warp == 0) {
        float hv = (lane < 8) ? cand[lane * 64] : FLT_MAX;
        int   hp = 0;
        for (int t = 0; t < kp1; t++) {
            float m = hv; int widx = lane;
            #pragma unroll
            for (int o = 16; o > 0; o >>= 1) {
                float om = __shfl_xor_sync(0xffffffffu, m, o);
                int   oi = __shfl_xor_sync(0xffffffffu, widx, o);
                if (om < m || (om == m && oi < widx)) { m = om; widx = oi; }
            }
            if (lane == 0) topd[t] = m;
            if (lane == widx) {
                hp++;
                hv = (hp < kp1) ? cand[lane * 64 + hp] : FLT_MAX;
            }
        }
        __syncwarp();

        // LID: drop nearest (topd[0]); d_i = sqrt(topd[i]), i in [1, kp1)
        float dk = sqrtf(fmaxf(topd[kp1 - 1], 0.f));
        float s = 0.f;
        for (int i = lane; i < kp1; i += 32)
            if (i >= 1) s += logf(sqrtf(fmaxf(topd[i], 0.f)) / dk);
        #pragma unroll
        for (int o = 16; o > 0; o >>= 1) s += __shfl_xor_sync(0xffffffffu, s, o);
        if (lane == 0) g_lid[b * 4 + l] = -(float)kk / s;
    }
}

// ---------------- kernel 5: linear head + sigmoid ----------------
__global__ void final_kernel(const float* __restrict__ w,
                             const float* __restrict__ bb,
                             float* __restrict__ out)
{
    int b = threadIdx.x;
    float z = bb[0];
    #pragma unroll
    for (int j = 0; j < 4; j++) z += g_lid[b * 4 + j] * w[j];
    out[b] = 1.f / (1.f + expf(-z));
}

// ---------------- launch ----------------
extern "C" void kernel_launch(void* const* d_in, const int* in_sizes, int n_in,
                              void* d_out, int out_size)
{
    const float* feat[4] = {0, 0, 0, 0};
    const float* ref[4]  = {0, 0, 0, 0};
    const float* rw = 0;
    const float* rb = 0;
    const int*   kp = 0;
    int ones = 0;
    for (int i = 0; i < n_in; i++) {
        switch (in_sizes[i]) {
            case 51380224: feat[0] = (const float*)d_in[i]; break;
            case 25690112: feat[1] = (const float*)d_in[i]; break;
            case 12845056: feat[2] = (const float*)d_in[i]; break;
            case 6422528:  feat[3] = (const float*)d_in[i]; break;
            case 128000:   ref[0]  = (const float*)d_in[i]; break;
            case 256000:   ref[1]  = (const float*)d_in[i]; break;
            case 512000:   ref[2]  = (const float*)d_in[i]; break;
            case 1024000:  ref[3]  = (const float*)d_in[i]; break;
            case 4:        rw      = (const float*)d_in[i]; break;
            case 1:
                if (ones++ == 0) rb = (const float*)d_in[i];
                else             kp = (const int*)d_in[i];
                break;
            default: break;
        }
    }

    pool_kernel<<<30720, 256>>>(feat[0], feat[1], feat[2], feat[3]);
    norms_kernel<<<1128, 256>>>(ref[0], ref[1], ref[2], ref[3]);

    dim3 gg(NRP / 64, NB / 64, 4);   // (32, 4, 4)
    dim3 bt(16, 16);
    dist_gemm_kernel<<<gg, bt>>>(ref[0], ref[1], ref[2], ref[3]);

    dim3 gs(NB, 4);
    select_kernel<<<gs, 256>>>(kp);

    final_kernel<<<1, 256>>>(rw, rb, (float*)d_out);
}

// round 4
// speedup vs baseline: 1.4221x; 1.4221x over previous
#include <cuda_runtime.h>
#include <math.h>
#include <float.h>

// layers: C = {64,128,256,512}, HW = {3136,784,196,49}, B=256, R=2000
#define NB 256
#define NR 2000
#define NRP 2048

__constant__ int c_C[4]    = {64, 128, 256, 512};
__constant__ int c_HW[4]   = {3136, 784, 196, 49};
__constant__ int c_qoff[4] = {0, 16384, 49152, 114688};

// scratch (static device globals; no allocation)
__device__ __align__(16) float g_fq[245760];        // pooled queries
__device__ __align__(16) float g_dot[4 * NB * NRP]; // q . ref^T, padded
__device__ float g_r2[4 * NR];
__device__ float g_q2[4 * NB];
__device__ float g_lid[NB * 4];

// ---------------- kernel 1: spatial mean pooling (warp per (b,c) row) ----------------
__global__ void __launch_bounds__(256) pool_kernel(
    const float* __restrict__ f0, const float* __restrict__ f1,
    const float* __restrict__ f2, const float* __restrict__ f3)
{
    int gw   = (blockIdx.x * 256 + threadIdx.x) >> 5;
    int lane = threadIdx.x & 31;
    if (gw >= 245760) return;

    int l, base;
    if      (gw < 16384)  { l = 0; base = 0; }
    else if (gw < 49152)  { l = 1; base = 16384; }
    else if (gw < 114688) { l = 2; base = 49152; }
    else                  { l = 3; base = 114688; }
    int row = gw - base;
    const float* f = (l == 0) ? f0 : (l == 1) ? f1 : (l == 2) ? f2 : f3;
    int HW = c_HW[l];
    const float* src = f + (size_t)row * HW;

    float s = 0.f;
    if (l < 3) {
        const float4* s4 = (const float4*)src;
        int n4 = HW >> 2;
        #pragma unroll 4
        for (int i = lane; i < n4; i += 32) {
            float4 v = s4[i];
            s += (v.x + v.y) + (v.z + v.w);
        }
    } else {
        #pragma unroll 2
        for (int i = lane; i < HW; i += 32) s += src[i];
    }
    #pragma unroll
    for (int o = 16; o > 0; o >>= 1) s += __shfl_xor_sync(0xffffffffu, s, o);
    if (lane == 0) g_fq[c_qoff[l] + row] = s / (float)HW;
}

// ---------------- kernel 2: squared norms of refs and pooled queries ----------------
__global__ void __launch_bounds__(256) norms_kernel(
    const float* __restrict__ r0, const float* __restrict__ r1,
    const float* __restrict__ r2, const float* __restrict__ r3)
{
    int gw   = (blockIdx.x * 256 + threadIdx.x) >> 5;
    int lane = threadIdx.x & 31;
    if (gw >= 9024) return;

    const float* src;
    float* out;
    int C;
    if (gw < 8000) {
        int l = gw / NR, row = gw % NR;
        const float* rp = (l == 0) ? r0 : (l == 1) ? r1 : (l == 2) ? r2 : r3;
        C = c_C[l];
        src = rp + (size_t)row * C;
        out = g_r2 + l * NR + row;
    } else {
        int idx = gw - 8000;
        int l = idx >> 8, row = idx & 255;
        C = c_C[l];
        src = g_fq + c_qoff[l] + (size_t)row * C;
        out = g_q2 + l * NB + row;
    }
    float s = 0.f;
    const float4* s4 = (const float4*)src;
    int n4 = C >> 2;
    #pragma unroll 4
    for (int i = lane; i < n4; i += 32) {
        float4 v = s4[i];
        s += v.x * v.x + v.y * v.y + v.z * v.z + v.w * v.w;
    }
    #pragma unroll
    for (int o = 16; o > 0; o >>= 1) s += __shfl_xor_sync(0xffffffffu, s, o);
    if (lane == 0) *out = s;
}

// ---------------- kernel 3: dot products q . ref^T (round-2 proven 32x64 tile) ----------------
__global__ void __launch_bounds__(256) dist_gemm_kernel(
    const float* __restrict__ r0, const float* __restrict__ r1,
    const float* __restrict__ r2, const float* __restrict__ r3)
{
    int l = blockIdx.z;
    int C = c_C[l];
    const float* ref = (l == 0) ? r0 : (l == 1) ? r1 : (l == 2) ? r2 : r3;
    const float* q   = g_fq + c_qoff[l];

    int bt = blockIdx.y << 5;   // batch tile base (32)
    int rt = blockIdx.x << 6;   // ref tile base (64)

    __shared__ float qs[16][33];
    __shared__ __align__(16) float rs[16][68];

    int tx = threadIdx.x, ty = threadIdx.y;
    int tid = ty * 16 + tx;

    float acc[2][4];
    #pragma unroll
    for (int i = 0; i < 2; i++)
        #pragma unroll
        for (int j = 0; j < 4; j++) acc[i][j] = 0.f;

    for (int c0 = 0; c0 < C; c0 += 16) {
        #pragma unroll
        for (int i = 0; i < 2; i++) {
            int idx = tid + i * 256;
            int b = idx >> 4, kk = idx & 15;
            qs[kk][b] = q[(size_t)(bt + b) * C + c0 + kk];
        }
        #pragma unroll
        for (int i = 0; i < 4; i++) {
            int idx = tid + i * 256;
            int r = idx >> 4, kk = idx & 15;
            int rr = rt + r;
            rs[kk][r] = (rr < NR) ? ref[(size_t)rr * C + c0 + kk] : 0.f;
        }
        __syncthreads();
        #pragma unroll
        for (int kk = 0; kk < 16; kk++) {
            float q0 = qs[kk][ty * 2];
            float q1 = qs[kk][ty * 2 + 1];
            float4 rv = *(const float4*)&rs[kk][tx * 4];
            acc[0][0] += q0 * rv.x; acc[0][1] += q0 * rv.y;
            acc[0][2] += q0 * rv.z; acc[0][3] += q0 * rv.w;
            acc[1][0] += q1 * rv.x; acc[1][1] += q1 * rv.y;
            acc[1][2] += q1 * rv.z; acc[1][3] += q1 * rv.w;
        }
        __syncthreads();
    }

    float* out = g_dot + ((size_t)l * NB + bt) * NRP + rt;
    #pragma unroll
    for (int i = 0; i < 2; i++) {
        int b = ty * 2 + i;
        *(float4*)&out[(size_t)b * NRP + tx * 4] =
            make_float4(acc[i][0], acc[i][1], acc[i][2], acc[i][3]);
    }
}

// ---------------- kernel 4: register-resident extraction, 1 barrier/round ----------------
__global__ void __launch_bounds__(256) select_kernel(const int* __restrict__ kp)
{
    int b = blockIdx.x;
    int l = blockIdx.y;
    int tid  = threadIdx.x;
    int warp = tid >> 5;
    int lane = tid & 31;

    __shared__ float wv[2][8];   // per-warp winner value (double-buffered by round parity)
    __shared__ int   wi[2][8];   // per-warp winner id
    __shared__ float topd[64];

    const float* dotp = g_dot + ((size_t)l * NB + b) * NRP;
    const float* r2p  = g_r2 + l * NR;
    float q2v = g_q2[l * NB + b];

    // each thread owns 8 contiguous distances in registers
    int base = tid * 8;
    float4 d0 = *(const float4*)&dotp[base];
    float4 d1 = *(const float4*)&dotp[base + 4];
    float dd[8] = {d0.x, d0.y, d0.z, d0.w, d1.x, d1.y, d1.z, d1.w};
    float v[8];
    #pragma unroll
    for (int j = 0; j < 8; j++) {
        int r = base + j;
        v[j] = (r < NR) ? fmaxf(q2v + r2p[r] - 2.f * dd[j], 0.f) : FLT_MAX;
    }

    int kk  = *kp;
    int kp1 = min(kk + 1, 64);

    for (int t = 0; t < kp1; t++) {
        // local min over 8 register slots
        float m = v[0]; int slot = 0;
        #pragma unroll
        for (int j = 1; j < 8; j++) if (v[j] < m) { m = v[j]; slot = j; }
        int id = (tid << 3) | slot;
        // warp argmin
        #pragma unroll
        for (int o = 16; o > 0; o >>= 1) {
            float om = __shfl_xor_sync(0xffffffffu, m, o);
            int   oi = __shfl_xor_sync(0xffffffffu, id, o);
            if (om < m) { m = om; id = oi; }
        }
        int p = t & 1;
        if (lane == 0) { wv[p][warp] = m; wi[p][warp] = id; }
        __syncthreads();
        // every thread redundantly picks block winner from 8 smem values
        float bm = wv[p][0]; int bi = wi[p][0];
        #pragma unroll
        for (int w = 1; w < 8; w++) {
            float x = wv[p][w];
            if (x < bm) { bm = x; bi = wi[p][w]; }
        }
        if (tid == 0) topd[t] = bm;
        if ((bi >> 3) == tid) {
            int s = bi & 7;
            #pragma unroll
            for (int j = 0; j < 8; j++) if (s == j) v[j] = FLT_MAX;
        }
        // no second barrier: next round writes the other buffer, and any
        // write to THIS buffer is two rounds away, past the next barrier.
    }
    __syncthreads();

    // LID: drop nearest (topd[0]); d_i = sqrt(topd[i]), d_k = sqrt(topd[kp1-1])
    if (warp == 0) {
        float dk = sqrtf(topd[kp1 - 1]);
        float s = 0.f;
        for (int i = lane; i < kp1; i += 32)
            if (i >= 1) s += logf(sqrtf(topd[i]) / dk);
        #pragma unroll
        for (int o = 16; o > 0; o >>= 1) s += __shfl_xor_sync(0xffffffffu, s, o);
        if (lane == 0) g_lid[b * 4 + l] = -(float)kk / s;
    }
}

// ---------------- kernel 5: linear head + sigmoid ----------------
__global__ void final_kernel(const float* __restrict__ w,
                             const float* __restrict__ bb,
                             float* __restrict__ out)
{
    int b = threadIdx.x;
    float z = bb[0];
    #pragma unroll
    for (int j = 0; j < 4; j++) z += g_lid[b * 4 + j] * w[j];
    out[b] = 1.f / (1.f + expf(-z));
}

// ---------------- launch ----------------
extern "C" void kernel_launch(void* const* d_in, const int* in_sizes, int n_in,
                              void* d_out, int out_size)
{
    const float* feat[4] = {0, 0, 0, 0};
    const float* ref[4]  = {0, 0, 0, 0};
    const float* rw = 0;
    const float* rb = 0;
    const int*   kp = 0;
    int ones = 0;
    for (int i = 0; i < n_in; i++) {
        switch (in_sizes[i]) {
            case 51380224: feat[0] = (const float*)d_in[i]; break;
            case 25690112: feat[1] = (const float*)d_in[i]; break;
            case 12845056: feat[2] = (const float*)d_in[i]; break;
            case 6422528:  feat[3] = (const float*)d_in[i]; break;
            case 128000:   ref[0]  = (const float*)d_in[i]; break;
            case 256000:   ref[1]  = (const float*)d_in[i]; break;
            case 512000:   ref[2]  = (const float*)d_in[i]; break;
            case 1024000:  ref[3]  = (const float*)d_in[i]; break;
            case 4:        rw      = (const float*)d_in[i]; break;
            case 1:
                if (ones++ == 0) rb = (const float*)d_in[i];
                else             kp = (const int*)d_in[i];
                break;
            default: break;
        }
    }

    pool_kernel<<<30720, 256>>>(feat[0], feat[1], feat[2], feat[3]);
    norms_kernel<<<1128, 256>>>(ref[0], ref[1], ref[2], ref[3]);

    dim3 gg(NRP / 64, NB / 32, 4);   // (32, 8, 4)
    dim3 bt(16, 16);
    dist_gemm_kernel<<<gg, bt>>>(ref[0], ref[1], ref[2], ref[3]);

    dim3 gs(NB, 4);
    select_kernel<<<gs, 256>>>(kp);

    final_kernel<<<1, 256>>>(rw, rb, (float*)d_out);
}

// round 6
// speedup vs baseline: 1.6055x; 1.1289x over previous
#include <cuda_runtime.h>
#include <math.h>
#include <float.h>

// layers: C = {64,128,256,512}, HW = {3136,784,196,49}, B=256, R=2000
#define NB 256
#define NR 2000
#define NRP 2048

__constant__ int c_C[4]    = {64, 128, 256, 512};
__constant__ int c_HW[4]   = {3136, 784, 196, 49};
__constant__ int c_qoff[4] = {0, 16384, 49152, 114688};

// scratch (static device globals; no allocation)
__device__ __align__(16) float g_fq[245760];        // pooled queries
__device__ __align__(16) float g_dot[4 * NB * NRP]; // q . ref^T, padded
__device__ float g_r2[4 * NR];
__device__ float g_q2[4 * NB];
__device__ float g_lid[NB * 4];

// ---------------- kernel 1: spatial mean pooling (unchanged from 176us run) ----------------
__global__ void __launch_bounds__(256) pool_kernel(
    const float* __restrict__ f0, const float* __restrict__ f1,
    const float* __restrict__ f2, const float* __restrict__ f3)
{
    int gw   = (blockIdx.x * 256 + threadIdx.x) >> 5;
    int lane = threadIdx.x & 31;
    if (gw >= 245760) return;

    int l, base;
    if      (gw < 16384)  { l = 0; base = 0; }
    else if (gw < 49152)  { l = 1; base = 16384; }
    else if (gw < 114688) { l = 2; base = 49152; }
    else                  { l = 3; base = 114688; }
    int row = gw - base;
    const float* f = (l == 0) ? f0 : (l == 1) ? f1 : (l == 2) ? f2 : f3;
    int HW = c_HW[l];
    const float* src = f + (size_t)row * HW;

    float s = 0.f;
    if (l < 3) {
        const float4* s4 = (const float4*)src;
        int n4 = HW >> 2;
        #pragma unroll 4
        for (int i = lane; i < n4; i += 32) {
            float4 v = s4[i];
            s += (v.x + v.y) + (v.z + v.w);
        }
    } else {
        #pragma unroll 2
        for (int i = lane; i < HW; i += 32) s += src[i];
    }
    #pragma unroll
    for (int o = 16; o > 0; o >>= 1) s += __shfl_xor_sync(0xffffffffu, s, o);
    if (lane == 0) g_fq[c_qoff[l] + row] = s / (float)HW;
}

// ---------------- kernel 2: squared norms (unchanged) ----------------
__global__ void __launch_bounds__(256) norms_kernel(
    const float* __restrict__ r0, const float* __restrict__ r1,
    const float* __restrict__ r2, const float* __restrict__ r3)
{
    int gw   = (blockIdx.x * 256 + threadIdx.x) >> 5;
    int lane = threadIdx.x & 31;
    if (gw >= 9024) return;

    const float* src;
    float* out;
    int C;
    if (gw < 8000) {
        int l = gw / NR, row = gw % NR;
        const float* rp = (l == 0) ? r0 : (l == 1) ? r1 : (l == 2) ? r2 : r3;
        C = c_C[l];
        src = rp + (size_t)row * C;
        out = g_r2 + l * NR + row;
    } else {
        int idx = gw - 8000;
        int l = idx >> 8, row = idx & 255;
        C = c_C[l];
        src = g_fq + c_qoff[l] + (size_t)row * C;
        out = g_q2 + l * NB + row;
    }
    float s = 0.f;
    const float4* s4 = (const float4*)src;
    int n4 = C >> 2;
    #pragma unroll 4
    for (int i = lane; i < n4; i += 32) {
        float4 v = s4[i];
        s += v.x * v.x + v.y * v.y + v.z * v.z + v.w * v.w;
    }
    #pragma unroll
    for (int o = 16; o > 0; o >>= 1) s += __shfl_xor_sync(0xffffffffu, s, o);
    if (lane == 0) *out = s;
}

// ---------------- kernel 3: 64x64 tile, kchunk 8, double-buffered ----------------
__global__ void __launch_bounds__(256) dist_gemm_kernel(
    const float* __restrict__ r0, const float* __restrict__ r1,
    const float* __restrict__ r2, const float* __restrict__ r3)
{
    int l = blockIdx.z;
    int C = c_C[l];
    const float* ref = (l == 0) ? r0 : (l == 1) ? r1 : (l == 2) ? r2 : r3;
    const float* q   = g_fq + c_qoff[l];

    int bt = blockIdx.y << 6;   // batch tile (64)
    int rt = blockIdx.x << 6;   // ref tile (64)

    __shared__ __align__(16) float qs[2][8][68];
    __shared__ __align__(16) float rs[2][8][68];

    int tx = threadIdx.x, ty = threadIdx.y;
    int tid = ty * 16 + tx;

    // loader role: threads 0..127 load q tile, 128..255 load r tile
    int isR  = tid >> 7;
    int lrow = (tid & 127) >> 1;   // 0..63
    int lkg  = tid & 1;            // k-group (4 floats)

    const float* gsrc;
    size_t gbase;
    int valid;
    if (isR) {
        int rr = rt + lrow;
        valid = (rr < NR);
        gbase = (size_t)(valid ? rr : 0) * C;
        gsrc  = ref;
    } else {
        valid = 1;
        gbase = (size_t)(bt + lrow) * C;
        gsrc  = q;
    }
    float* sdst0 = (isR ? &rs[0][0][0] : &qs[0][0][0]) + (lkg * 4) * 68 + lrow;
    float* sdst1 = (isR ? &rs[1][0][0] : &qs[1][0][0]) + (lkg * 4) * 68 + lrow;

    float acc[4][4];
    #pragma unroll
    for (int i = 0; i < 4; i++)
        #pragma unroll
        for (int j = 0; j < 4; j++) acc[i][j] = 0.f;

    // prologue: chunk 0 -> buffer 0
    {
        float4 v = valid ? *(const float4*)&gsrc[gbase + lkg * 4]
                         : make_float4(0.f, 0.f, 0.f, 0.f);
        sdst0[0]      = v.x;
        sdst0[68]     = v.y;
        sdst0[2 * 68] = v.z;
        sdst0[3 * 68] = v.w;
    }

    int nch = C >> 3;
    for (int ch = 0; ch < nch; ch++) {
        __syncthreads();
        int buf = ch & 1;

        // prefetch next chunk into regs
        float4 nx = make_float4(0.f, 0.f, 0.f, 0.f);
        if (ch + 1 < nch && valid)
            nx = *(const float4*)&gsrc[gbase + (ch + 1) * 8 + lkg * 4];

        // compute chunk ch
        #pragma unroll
        for (int kk = 0; kk < 8; kk++) {
            float4 qv = *(const float4*)&qs[buf][kk][ty * 4];
            float4 rv = *(const float4*)&rs[buf][kk][tx * 4];
            acc[0][0] += qv.x * rv.x; acc[0][1] += qv.x * rv.y;
            acc[0][2] += qv.x * rv.z; acc[0][3] += qv.x * rv.w;
            acc[1][0] += qv.y * rv.x; acc[1][1] += qv.y * rv.y;
            acc[1][2] += qv.y * rv.z; acc[1][3] += qv.y * rv.w;
            acc[2][0] += qv.z * rv.x; acc[2][1] += qv.z * rv.y;
            acc[2][2] += qv.z * rv.z; acc[2][3] += qv.z * rv.w;
            acc[3][0] += qv.w * rv.x; acc[3][1] += qv.w * rv.y;
            acc[3][2] += qv.w * rv.z; acc[3][3] += qv.w * rv.w;
        }

        // store next chunk into other buffer (its prior contents were consumed
        // in iteration ch-1, before this iteration's barrier)
        if (ch + 1 < nch) {
            float* d = buf ? sdst0 : sdst1;
            d[0]      = nx.x;
            d[68]     = nx.y;
            d[2 * 68] = nx.z;
            d[3 * 68] = nx.w;
        }
    }

    float* out = g_dot + ((size_t)l * NB + bt) * NRP + rt;
    #pragma unroll
    for (int i = 0; i < 4; i++) {
        *(float4*)&out[(size_t)(ty * 4 + i) * NRP + tx * 4] =
            make_float4(acc[i][0], acc[i][1], acc[i][2], acc[i][3]);
    }
}

// ---------------- kernel 4: extraction with uint mins + REDUX ----------------
__global__ void __launch_bounds__(256) select_kernel(const int* __restrict__ kp)
{
    int b = blockIdx.x;
    int l = blockIdx.y;
    int tid  = threadIdx.x;
    int warp = tid >> 5;
    int lane = tid & 31;

    __shared__ unsigned wv[2][8];  // per-warp min bits, double-buffered by parity
    __shared__ float topd[64];

    const float* dotp = g_dot + ((size_t)l * NB + b) * NRP;
    const float* r2p  = g_r2 + l * NR;
    float q2v = g_q2[l * NB + b];

    int base = tid * 8;
    float4 d0 = *(const float4*)&dotp[base];
    float4 d1 = *(const float4*)&dotp[base + 4];
    float dd[8] = {d0.x, d0.y, d0.z, d0.w, d1.x, d1.y, d1.z, d1.w};
    unsigned u[8];
    #pragma unroll
    for (int j = 0; j < 8; j++) {
        int r = base + j;
        float x = (r < NR) ? fmaxf(q2v + r2p[r] - 2.f * dd[j], 0.f) : FLT_MAX;
        u[j] = __float_as_uint(x);   // nonneg floats: bit order == value order
    }

    int kk  = *kp;
    int kp1 = min(kk + 1, 64);

    for (int t = 0; t < kp1; t++) {
        // local min over 8 slots, 3-level tree
        unsigned a0 = min(u[0], u[1]), a1 = min(u[2], u[3]);
        unsigned a2 = min(u[4], u[5]), a3 = min(u[6], u[7]);
        unsigned lm = min(min(a0, a1), min(a2, a3));
        // warp min in one REDUX
        unsigned wm = __reduce_min_sync(0xffffffffu, lm);
        unsigned bal = __ballot_sync(0xffffffffu, lm == wm);
        bool leader = (lane == (__ffs(bal) - 1));
        int p = t & 1;
        if (lane == 0) wv[p][warp] = wm;
        __syncthreads();
        // block min over 8 warp-mins (all threads redundantly)
        unsigned bm = wv[p][0]; int bw = 0;
        #pragma unroll
        for (int w = 1; w < 8; w++) {
            unsigned x = wv[p][w];
            if (x < bm) { bm = x; bw = w; }
        }
        if (tid == 0) topd[t] = __uint_as_float(bm);
        if (warp == bw && leader) {
            bool done = false;
            #pragma unroll
            for (int j = 0; j < 8; j++)
                if (!done && u[j] == wm) { u[j] = 0xFFFFFFFFu; done = true; }
        }
        // no second barrier: next round uses the other parity buffer
    }
    __syncthreads();

    if (warp == 0) {
        float dk = sqrtf(topd[kp1 - 1]);
        float s = 0.f;
        for (int i = lane; i < kp1; i += 32)
            if (i >= 1) s += logf(sqrtf(topd[i]) / dk);
        #pragma unroll
        for (int o = 16; o > 0; o >>= 1) s += __shfl_xor_sync(0xffffffffu, s, o);
        if (lane == 0) g_lid[b * 4 + l] = -(float)kk / s;
    }
}

// ---------------- kernel 5: linear head + sigmoid ----------------
__global__ void final_kernel(const float* __restrict__ w,
                             const float* __restrict__ bb,
                             float* __restrict__ out)
{
    int b = threadIdx.x;
    float z = bb[0];
    #pragma unroll
    for (int j = 0; j < 4; j++) z += g_lid[b * 4 + j] * w[j];
    out[b] = 1.f / (1.f + expf(-z));
}

// ---------------- launch ----------------
extern "C" void kernel_launch(void* const* d_in, const int* in_sizes, int n_in,
                              void* d_out, int out_size)
{
    const float* feat[4] = {0, 0, 0, 0};
    const float* ref[4]  = {0, 0, 0, 0};
    const float* rw = 0;
    const float* rb = 0;
    const int*   kp = 0;
    int ones = 0;
    for (int i = 0; i < n_in; i++) {
        switch (in_sizes[i]) {
            case 51380224: feat[0] = (const float*)d_in[i]; break;
            case 25690112: feat[1] = (const float*)d_in[i]; break;
            case 12845056: feat[2] = (const float*)d_in[i]; break;
            case 6422528:  feat[3] = (const float*)d_in[i]; break;
            case 128000:   ref[0]  = (const float*)d_in[i]; break;
            case 256000:   ref[1]  = (const float*)d_in[i]; break;
            case 512000:   ref[2]  = (const float*)d_in[i]; break;
            case 1024000:  ref[3]  = (const float*)d_in[i]; break;
            case 4:        rw      = (const float*)d_in[i]; break;
            case 1:
                if (ones++ == 0) rb = (const float*)d_in[i];
                else             kp = (const int*)d_in[i];
                break;
            default: break;
        }
    }

    pool_kernel<<<30720, 256>>>(feat[0], feat[1], feat[2], feat[3]);
    norms_kernel<<<1128, 256>>>(ref[0], ref[1], ref[2], ref[3]);

    dim3 gg(NRP / 64, NB / 64, 4);   // (32, 4, 4) = 512 blocks
    dim3 bt(16, 16);
    dist_gemm_kernel<<<gg, bt>>>(ref[0], ref[1], ref[2], ref[3]);

    dim3 gs(NB, 4);
    select_kernel<<<gs, 256>>>(kp);

    final_kernel<<<1, 256>>>(rw, rb, (float*)d_out);
}

// round 8
// speedup vs baseline: 1.6680x; 1.0390x over previous
#include <cuda_runtime.h>
#include <math.h>
#include <float.h>

// layers: C = {64,128,256,512}, HW = {3136,784,196,49}, B=256, R=2000
#define NB 256
#define NR 2000
#define NRP 2048

__constant__ int c_C[4]    = {64, 128, 256, 512};
__constant__ int c_HW[4]   = {3136, 784, 196, 49};
__constant__ int c_qoff[4] = {0, 16384, 49152, 114688};

// scratch (static device globals; no allocation)
__device__ __align__(16) float g_fq[245760];        // pooled queries
__device__ __align__(16) float g_dot[4 * NB * NRP]; // q . ref^T, padded
__device__ float g_r2[4 * NR];
__device__ float g_q2[4 * NB];
__device__ float g_lid[NB * 4];

// ---------------- kernel 1: spatial mean pooling (unchanged) ----------------
__global__ void __launch_bounds__(256) pool_kernel(
    const float* __restrict__ f0, const float* __restrict__ f1,
    const float* __restrict__ f2, const float* __restrict__ f3)
{
    int gw   = (blockIdx.x * 256 + threadIdx.x) >> 5;
    int lane = threadIdx.x & 31;
    if (gw >= 245760) return;

    int l, base;
    if      (gw < 16384)  { l = 0; base = 0; }
    else if (gw < 49152)  { l = 1; base = 16384; }
    else if (gw < 114688) { l = 2; base = 49152; }
    else                  { l = 3; base = 114688; }
    int row = gw - base;
    const float* f = (l == 0) ? f0 : (l == 1) ? f1 : (l == 2) ? f2 : f3;
    int HW = c_HW[l];
    const float* src = f + (size_t)row * HW;

    float s = 0.f;
    if (l < 3) {
        const float4* s4 = (const float4*)src;
        int n4 = HW >> 2;
        #pragma unroll 4
        for (int i = lane; i < n4; i += 32) {
            float4 v = s4[i];
            s += (v.x + v.y) + (v.z + v.w);
        }
    } else {
        #pragma unroll 2
        for (int i = lane; i < HW; i += 32) s += src[i];
    }
    #pragma unroll
    for (int o = 16; o > 0; o >>= 1) s += __shfl_xor_sync(0xffffffffu, s, o);
    if (lane == 0) g_fq[c_qoff[l] + row] = s / (float)HW;
}

// ---------------- kernel 2: squared norms (unchanged) ----------------
__global__ void __launch_bounds__(256) norms_kernel(
    const float* __restrict__ r0, const float* __restrict__ r1,
    const float* __restrict__ r2, const float* __restrict__ r3)
{
    int gw   = (blockIdx.x * 256 + threadIdx.x) >> 5;
    int lane = threadIdx.x & 31;
    if (gw >= 9024) return;

    const float* src;
    float* out;
    int C;
    if (gw < 8000) {
        int l = gw / NR, row = gw % NR;
        const float* rp = (l == 0) ? r0 : (l == 1) ? r1 : (l == 2) ? r2 : r3;
        C = c_C[l];
        src = rp + (size_t)row * C;
        out = g_r2 + l * NR + row;
    } else {
        int idx = gw - 8000;
        int l = idx >> 8, row = idx & 255;
        C = c_C[l];
        src = g_fq + c_qoff[l] + (size_t)row * C;
        out = g_q2 + l * NB + row;
    }
    float s = 0.f;
    const float4* s4 = (const float4*)src;
    int n4 = C >> 2;
    #pragma unroll 4
    for (int i = lane; i < n4; i += 32) {
        float4 v = s4[i];
        s += v.x * v.x + v.y * v.y + v.z * v.z + v.w * v.w;
    }
    #pragma unroll
    for (int o = 16; o > 0; o >>= 1) s += __shfl_xor_sync(0xffffffffu, s, o);
    if (lane == 0) *out = s;
}

// ---------------- kernel 3: 64x64 tile, K-chunk 16, double-buffered, heavy-first ----------------
__global__ void __launch_bounds__(256) dist_gemm_kernel(
    const float* __restrict__ r0, const float* __restrict__ r1,
    const float* __restrict__ r2, const float* __restrict__ r3)
{
    int l = 3 - blockIdx.z;     // heavy layers (big C) launch first -> short tail
    int C = c_C[l];
    const float* ref = (l == 0) ? r0 : (l == 1) ? r1 : (l == 2) ? r2 : r3;
    const float* q   = g_fq + c_qoff[l];

    int bt = blockIdx.y << 6;   // batch tile (64)
    int rt = blockIdx.x << 6;   // ref tile (64)

    __shared__ __align__(16) float qs[2][16][68];
    __shared__ __align__(16) float rs[2][16][68];

    int tx = threadIdx.x, ty = threadIdx.y;
    int tid = ty * 16 + tx;

    // loader role: threads 0..127 load q tile, 128..255 load r tile
    // each thread: row = (tid&127)>>1, two float4s at k = kg*4 and k = 8+kg*4
    int isR  = tid >> 7;
    int lrow = (tid & 127) >> 1;   // 0..63
    int lkg  = tid & 1;            // 0/1

    const float* gsrc;
    size_t gbase;
    int valid;
    if (isR) {
        int rr = rt + lrow;
        valid = (rr < NR);
        gbase = (size_t)(valid ? rr : 0) * C;
        gsrc  = ref;
    } else {
        valid = 1;
        gbase = (size_t)(bt + lrow) * C;
        gsrc  = q;
    }
    // smem column-major-ish dst: [k][row]; two k-offsets per thread
    float* sb0 = (isR ? &rs[0][0][0] : &qs[0][0][0]) + (lkg * 4) * 68 + lrow;
    float* sb1 = (isR ? &rs[1][0][0] : &qs[1][0][0]) + (lkg * 4) * 68 + lrow;

    float acc[4][4];
    #pragma unroll
    for (int i = 0; i < 4; i++)
        #pragma unroll
        for (int j = 0; j < 4; j++) acc[i][j] = 0.f;

    // prologue: chunk 0 -> buffer 0
    {
        float4 a = make_float4(0.f, 0.f, 0.f, 0.f);
        float4 b = make_float4(0.f, 0.f, 0.f, 0.f);
        if (valid) {
            a = *(const float4*)&gsrc[gbase + lkg * 4];
            b = *(const float4*)&gsrc[gbase + 8 + lkg * 4];
        }
        sb0[0]       = a.x; sb0[68]      = a.y; sb0[2 * 68] = a.z; sb0[3 * 68] = a.w;
        sb0[8 * 68]  = b.x; sb0[9 * 68]  = b.y; sb0[10 * 68] = b.z; sb0[11 * 68] = b.w;
    }

    int nch = C >> 4;   // chunks of 16
    for (int ch = 0; ch < nch; ch++) {
        __syncthreads();
        int buf = ch & 1;

        // prefetch next chunk into regs
        float4 na = make_float4(0.f, 0.f, 0.f, 0.f);
        float4 nb = make_float4(0.f, 0.f, 0.f, 0.f);
        if (ch + 1 < nch && valid) {
            size_t o = gbase + (size_t)(ch + 1) * 16;
            na = *(const float4*)&gsrc[o + lkg * 4];
            nb = *(const float4*)&gsrc[o + 8 + lkg * 4];
        }

        // compute chunk ch: 16 k-steps x 16 FFMA
        #pragma unroll
        for (int kk = 0; kk < 16; kk++) {
            float4 qv = *(const float4*)&qs[buf][kk][ty * 4];
            float4 rv = *(const float4*)&rs[buf][kk][tx * 4];
            acc[0][0] += qv.x * rv.x; acc[0][1] += qv.x * rv.y;
            acc[0][2] += qv.x * rv.z; acc[0][3] += qv.x * rv.w;
            acc[1][0] += qv.y * rv.x; acc[1][1] += qv.y * rv.y;
            acc[1][2] += qv.y * rv.z; acc[1][3] += qv.y * rv.w;
            acc[2][0] += qv.z * rv.x; acc[2][1] += qv.z * rv.y;
            acc[2][2] += qv.z * rv.z; acc[2][3] += qv.z * rv.w;
            acc[3][0] += qv.w * rv.x; acc[3][1] += qv.w * rv.y;
            acc[3][2] += qv.w * rv.z; acc[3][3] += qv.w * rv.w;
        }

        // store prefetched chunk into the other buffer (consumed pre-barrier)
        if (ch + 1 < nch) {
            float* d = buf ? sb0 : sb1;
            d[0]       = na.x; d[68]      = na.y; d[2 * 68]  = na.z; d[3 * 68]  = na.w;
            d[8 * 68]  = nb.x; d[9 * 68]  = nb.y; d[10 * 68] = nb.z; d[11 * 68] = nb.w;
        }
    }

    float* out = g_dot + ((size_t)l * NB + bt) * NRP + rt;
    #pragma unroll
    for (int i = 0; i < 4; i++) {
        *(float4*)&out[(size_t)(ty * 4 + i) * NRP + tx * 4] =
            make_float4(acc[i][0], acc[i][1], acc[i][2], acc[i][3]);
    }
}

// ---------------- kernel 4: extraction with uint mins + REDUX (unchanged) ----------------
__global__ void __launch_bounds__(256) select_kernel(const int* __restrict__ kp)
{
    int b = blockIdx.x;
    int l = blockIdx.y;
    int tid  = threadIdx.x;
    int warp = tid >> 5;
    int lane = tid & 31;

    __shared__ unsigned wv[2][8];
    __shared__ float topd[64];

    const float* dotp = g_dot + ((size_t)l * NB + b) * NRP;
    const float* r2p  = g_r2 + l * NR;
    float q2v = g_q2[l * NB + b];

    int base = tid * 8;
    float4 d0 = *(const float4*)&dotp[base];
    float4 d1 = *(const float4*)&dotp[base + 4];
    float dd[8] = {d0.x, d0.y, d0.z, d0.w, d1.x, d1.y, d1.z, d1.w};
    unsigned u[8];
    #pragma unroll
    for (int j = 0; j < 8; j++) {
        int r = base + j;
        float x = (r < NR) ? fmaxf(q2v + r2p[r] - 2.f * dd[j], 0.f) : FLT_MAX;
        u[j] = __float_as_uint(x);
    }

    int kk  = *kp;
    int kp1 = min(kk + 1, 64);

    for (int t = 0; t < kp1; t++) {
        unsigned a0 = min(u[0], u[1]), a1 = min(u[2], u[3]);
        unsigned a2 = min(u[4], u[5]), a3 = min(u[6], u[7]);
        unsigned lm = min(min(a0, a1), min(a2, a3));
        unsigned wm = __reduce_min_sync(0xffffffffu, lm);
        unsigned bal = __ballot_sync(0xffffffffu, lm == wm);
        bool leader = (lane == (__ffs(bal) - 1));
        int p = t & 1;
        if (lane == 0) wv[p][warp] = wm;
        __syncthreads();
        unsigned bm = wv[p][0]; int bw = 0;
        #pragma unroll
        for (int w = 1; w < 8; w++) {
            unsigned x = wv[p][w];
            if (x < bm) { bm = x; bw = w; }
        }
        if (tid == 0) topd[t] = __uint_as_float(bm);
        if (warp == bw && leader) {
            bool done = false;
            #pragma unroll
            for (int j = 0; j < 8; j++)
                if (!done && u[j] == wm) { u[j] = 0xFFFFFFFFu; done = true; }
        }
    }
    __syncthreads();

    if (warp == 0) {
        float dk = sqrtf(topd[kp1 - 1]);
        float s = 0.f;
        for (int i = lane; i < kp1; i += 32)
            if (i >= 1) s += logf(sqrtf(topd[i]) / dk);
        #pragma unroll
        for (int o = 16; o > 0; o >>= 1) s += __shfl_xor_sync(0xffffffffu, s, o);
        if (lane == 0) g_lid[b * 4 + l] = -(float)kk / s;
    }
}

// ---------------- kernel 5: linear head + sigmoid ----------------
__global__ void final_kernel(const float* __restrict__ w,
                             const float* __restrict__ bb,
                             float* __restrict__ out)
{
    int b = threadIdx.x;
    float z = bb[0];
    #pragma unroll
    for (int j = 0; j < 4; j++) z += g_lid[b * 4 + j] * w[j];
    out[b] = 1.f / (1.f + expf(-z));
}

// ---------------- launch ----------------
extern "C" void kernel_launch(void* const* d_in, const int* in_sizes, int n_in,
                              void* d_out, int out_size)
{
    const float* feat[4] = {0, 0, 0, 0};
    const float* ref[4]  = {0, 0, 0, 0};
    const float* rw = 0;
    const float* rb = 0;
    const int*   kp = 0;
    int ones = 0;
    for (int i = 0; i < n_in; i++) {
        switch (in_sizes[i]) {
            case 51380224: feat[0] = (const float*)d_in[i]; break;
            case 25690112: feat[1] = (const float*)d_in[i]; break;
            case 12845056: feat[2] = (const float*)d_in[i]; break;
            case 6422528:  feat[3] = (const float*)d_in[i]; break;
            case 128000:   ref[0]  = (const float*)d_in[i]; break;
            case 256000:   ref[1]  = (const float*)d_in[i]; break;
            case 512000:   ref[2]  = (const float*)d_in[i]; break;
            case 1024000:  ref[3]  = (const float*)d_in[i]; break;
            case 4:        rw      = (const float*)d_in[i]; break;
            case 1:
                if (ones++ == 0) rb = (const float*)d_in[i];
                else             kp = (const int*)d_in[i];
                break;
            default: break;
        }
    }

    pool_kernel<<<30720, 256>>>(feat[0], feat[1], feat[2], feat[3]);
    norms_kernel<<<1128, 256>>>(ref[0], ref[1], ref[2], ref[3]);

    dim3 gg(NRP / 64, NB / 64, 4);   // (32, 4, 4) = 512 blocks; z reversed inside
    dim3 bt(16, 16);
    dist_gemm_kernel<<<gg, bt>>>(ref[0], ref[1], ref[2], ref[3]);

    dim3 gs(NB, 4);
    select_kernel<<<gs, 256>>>(kp);

    final_kernel<<<1, 256>>>(rw, rb, (float*)d_out);
}